// round 3
// baseline (speedup 1.0000x reference)
#include <cuda_runtime.h>
#include <cuda_bf16.h>

#define N_NODES 50000
#define N_EDGES 800000
#define FEATS   128
#define TILE_R  32

// Scratch for aggregated features (alloc-free rule: __device__ global).
__device__ float g_agg[(size_t)N_NODES * FEATS];

// ---------------------------------------------------------------------------
// Kernel 1: zero the aggregation buffer (in the captured graph so every replay
// starts from zeros — required for determinism).
// ---------------------------------------------------------------------------
__global__ void zero_agg_kernel() {
    int i = blockIdx.x * blockDim.x + threadIdx.x;
    const int n4 = (N_NODES * FEATS) / 4;
    float4* p = reinterpret_cast<float4*>(g_agg);
    if (i < n4) p[i] = make_float4(0.f, 0.f, 0.f, 0.f);
}

// ---------------------------------------------------------------------------
// Kernel 2: edge scatter. One warp per edge: gather features[src] (128 floats,
// float4 per lane, fully coalesced) and reduce into g_agg[dst] with vector
// red.global.add.v4.f32 — 8 RED.128 per edge instead of 128 RED.32.
// Indices are INT32 (JAX x64 disabled downcasts the reference's int64).
// ---------------------------------------------------------------------------
__global__ void scatter_kernel(const float* __restrict__ feat,
                               const int* __restrict__ src,
                               const int* __restrict__ dst) {
    int gtid = blockIdx.x * blockDim.x + threadIdx.x;
    int edge = gtid >> 5;
    int lane = threadIdx.x & 31;
    if (edge >= N_EDGES) return;

    int s = src[edge];   // broadcast load across warp
    int d = dst[edge];
    // Defensive: if dtype assumption were wrong, fail via rel_err not IMA.
    if ((unsigned)s >= N_NODES || (unsigned)d >= N_NODES) return;

    const float4* f4 = reinterpret_cast<const float4*>(feat + (size_t)s * FEATS);
    float4 v = f4[lane];

    float* ap = g_agg + (size_t)d * FEATS + lane * 4;
    asm volatile("red.global.add.v4.f32 [%0], {%1, %2, %3, %4};"
                 :: "l"(ap), "f"(v.x), "f"(v.y), "f"(v.z), "f"(v.w)
                 : "memory");
}

// ---------------------------------------------------------------------------
// Kernel 3: h = relu(agg @ W^T + bias).
// Block = 128 threads (one per output column), TILE_R=32 rows per block.
// Smem: Wt[k][col] (transposed weight, conflict-free scalar reads) = 64 KB,
//       As[32][128] row tile = 16 KB  -> 80 KB dynamic smem.
// ---------------------------------------------------------------------------
__global__ void gemm_bias_relu_kernel(const float* __restrict__ W,
                                      const float* __restrict__ bias,
                                      float* __restrict__ out) {
    extern __shared__ float sm[];
    float* Wt = sm;                       // [128][128], Wt[k*128 + c] = W[c*128 + k]
    float* As = sm + FEATS * FEATS;       // [TILE_R][128]

    const int col = threadIdx.x;          // 0..127
    const int row0 = blockIdx.x * TILE_R;

    for (int i = threadIdx.x; i < FEATS * FEATS; i += blockDim.x) {
        int k = i & (FEATS - 1);
        int c = i >> 7;
        Wt[k * FEATS + c] = W[c * FEATS + k];
    }
    for (int r = 0; r < TILE_R; r++) {
        int row = row0 + r;
        As[r * FEATS + col] = (row < N_NODES) ? g_agg[(size_t)row * FEATS + col] : 0.f;
    }
    __syncthreads();

    const float b = bias[col];

    for (int rb = 0; rb < TILE_R; rb += 8) {
        float acc[8];
        #pragma unroll
        for (int r = 0; r < 8; r++) acc[r] = 0.f;

        #pragma unroll 4
        for (int k = 0; k < FEATS; k += 4) {
            float w0 = Wt[(k + 0) * FEATS + col];
            float w1 = Wt[(k + 1) * FEATS + col];
            float w2 = Wt[(k + 2) * FEATS + col];
            float w3 = Wt[(k + 3) * FEATS + col];
            #pragma unroll
            for (int r = 0; r < 8; r++) {
                float4 a = *reinterpret_cast<const float4*>(&As[(rb + r) * FEATS + k]);
                acc[r] += w0 * a.x;
                acc[r] += w1 * a.y;
                acc[r] += w2 * a.z;
                acc[r] += w3 * a.w;
            }
        }

        #pragma unroll
        for (int r = 0; r < 8; r++) {
            int row = row0 + rb + r;
            if (row < N_NODES)
                out[(size_t)row * FEATS + col] = fmaxf(acc[r] + b, 0.f);
        }
    }
}

// ---------------------------------------------------------------------------
extern "C" void kernel_launch(void* const* d_in, const int* in_sizes, int n_in,
                              void* d_out, int out_size) {
    const float* feat = (const float*)d_in[0];   // [50000,128] f32
    const int*   src  = (const int*)d_in[1];     // [800000] i32
    const int*   dst  = (const int*)d_in[2];     // [800000] i32
    const float* W    = (const float*)d_in[3];   // [128,128] f32
    const float* bias = (const float*)d_in[4];   // [128] f32
    float*       out  = (float*)d_out;           // [50000,128] f32

    (void)in_sizes; (void)n_in; (void)out_size;

    const int smem_bytes = (FEATS * FEATS + TILE_R * FEATS) * sizeof(float); // 80 KB
    static bool attr_set = false;
    if (!attr_set) {
        cudaFuncSetAttribute(gemm_bias_relu_kernel,
                             cudaFuncAttributeMaxDynamicSharedMemorySize, smem_bytes);
        attr_set = true;
    }

    // 1) zero scratch
    {
        int n4 = (N_NODES * FEATS) / 4;
        zero_agg_kernel<<<(n4 + 255) / 256, 256>>>();
    }
    // 2) edge scatter (warp per edge)
    {
        long long threads = (long long)N_EDGES * 32;
        int blocks = (int)((threads + 255) / 256);
        scatter_kernel<<<blocks, 256>>>(feat, src, dst);
    }
    // 3) GEMM + bias + relu
    {
        int blocks = (N_NODES + TILE_R - 1) / TILE_R;
        gemm_bias_relu_kernel<<<blocks, FEATS, smem_bytes>>>(W, bias, out);
    }
}

// round 4
// speedup vs baseline: 1.3712x; 1.3712x over previous
#include <cuda_runtime.h>
#include <cuda_bf16.h>

#define N_NODES 50000
#define N_EDGES 800000
#define FEATS   128
#define TILE_R  32
#define WT_STRIDE 129   // padded smem stride: conflict-free transpose writes AND reads

// ---------------- device scratch (alloc-free rule: __device__ globals) -----
__device__ float g_xf[(size_t)N_NODES * FEATS];   // feat @ W^T
__device__ int   g_cnt[N_NODES + 1];              // per-dst degree
__device__ int   g_off[N_NODES + 1];              // CSR offsets
__device__ int   g_cur[N_NODES];                  // fill cursors
__device__ int   g_bucket[N_EDGES];               // src ids bucketed by dst

// ---------------------------------------------------------------------------
// K1: zero the degree counters (runs every replay — graph determinism).
// ---------------------------------------------------------------------------
__global__ void zero_cnt_kernel() {
    int i = blockIdx.x * blockDim.x + threadIdx.x;
    if (i <= N_NODES) g_cnt[i] = 0;
}

// ---------------------------------------------------------------------------
// K2: histogram of dst.
// ---------------------------------------------------------------------------
__global__ void hist_kernel(const int* __restrict__ dst) {
    int e = blockIdx.x * blockDim.x + threadIdx.x;
    if (e < N_EDGES) {
        int d = dst[e];
        if ((unsigned)d < N_NODES) atomicAdd(&g_cnt[d], 1);
    }
}

// ---------------------------------------------------------------------------
// K3: single-block exclusive scan of g_cnt -> g_off (and g_cur copy).
// 1024 threads, 49 tiles, warp-shuffle scan + smem carry.
// ---------------------------------------------------------------------------
__global__ void scan_kernel() {
    __shared__ int warp_sums[32];
    __shared__ int s_carry;
    int tid  = threadIdx.x;
    int lane = tid & 31;
    int wid  = tid >> 5;
    if (tid == 0) s_carry = 0;
    __syncthreads();

    for (int base = 0; base < N_NODES; base += 1024) {
        int idx = base + tid;
        int x = (idx < N_NODES) ? g_cnt[idx] : 0;

        int v = x;
        #pragma unroll
        for (int d = 1; d < 32; d <<= 1) {
            int t = __shfl_up_sync(0xffffffff, v, d);
            if (lane >= d) v += t;
        }
        if (lane == 31) warp_sums[wid] = v;
        __syncthreads();
        if (wid == 0) {
            int w = warp_sums[lane];
            #pragma unroll
            for (int d = 1; d < 32; d <<= 1) {
                int t = __shfl_up_sync(0xffffffff, w, d);
                if (lane >= d) w += t;
            }
            warp_sums[lane] = w;  // inclusive warp-sum scan
        }
        __syncthreads();

        int warp_off = (wid > 0) ? warp_sums[wid - 1] : 0;
        int incl = v + warp_off;
        int excl = incl - x;
        int carry = s_carry;
        if (idx < N_NODES) {
            g_off[idx] = carry + excl;
            g_cur[idx] = carry + excl;
        }
        int block_total = warp_sums[31];
        __syncthreads();                    // all reads of s_carry/warp_sums done
        if (tid == 0) s_carry = carry + block_total;
        __syncthreads();
    }
    if (tid == 0) g_off[N_NODES] = N_EDGES;
}

// ---------------------------------------------------------------------------
// K4: bucket fill — src ids grouped by dst.
// ---------------------------------------------------------------------------
__global__ void fill_kernel(const int* __restrict__ src,
                            const int* __restrict__ dst) {
    int e = blockIdx.x * blockDim.x + threadIdx.x;
    if (e < N_EDGES) {
        int d = dst[e];
        int s = src[e];
        if ((unsigned)d < N_NODES && (unsigned)s < N_NODES) {
            int pos = atomicAdd(&g_cur[d], 1);
            g_bucket[pos] = s;
        }
    }
}

// ---------------------------------------------------------------------------
// K5: xf = feat @ W^T (no bias/relu — applied in gather).
// Block = 128 threads (one per out col), 32 rows/block.
// Wt in smem with stride 129: conflict-free transpose writes and reads.
// ---------------------------------------------------------------------------
__global__ void gemm_kernel(const float* __restrict__ A,  // [N,128] feat
                            const float* __restrict__ W)  // [128,128]
{
    extern __shared__ float sm[];
    float* Wt = sm;                           // [128][129]
    float* As = sm + FEATS * WT_STRIDE;       // [TILE_R][128]

    const int col  = threadIdx.x;
    const int row0 = blockIdx.x * TILE_R;

    for (int i = threadIdx.x; i < FEATS * FEATS; i += blockDim.x) {
        int k = i & (FEATS - 1);
        int c = i >> 7;
        Wt[k * WT_STRIDE + c] = W[c * FEATS + k];   // lanes: consecutive k -> distinct banks
    }
    for (int r = 0; r < TILE_R; r++) {
        int row = row0 + r;
        As[r * FEATS + col] = (row < N_NODES) ? A[(size_t)row * FEATS + col] : 0.f;
    }
    __syncthreads();

    for (int rb = 0; rb < TILE_R; rb += 8) {
        float acc[8];
        #pragma unroll
        for (int r = 0; r < 8; r++) acc[r] = 0.f;

        #pragma unroll 4
        for (int k = 0; k < FEATS; k += 4) {
            float w0 = Wt[(k + 0) * WT_STRIDE + col];
            float w1 = Wt[(k + 1) * WT_STRIDE + col];
            float w2 = Wt[(k + 2) * WT_STRIDE + col];
            float w3 = Wt[(k + 3) * WT_STRIDE + col];
            #pragma unroll
            for (int r = 0; r < 8; r++) {
                float4 a = *reinterpret_cast<const float4*>(&As[(rb + r) * FEATS + k]);
                acc[r] += w0 * a.x;
                acc[r] += w1 * a.y;
                acc[r] += w2 * a.z;
                acc[r] += w3 * a.w;
            }
        }

        #pragma unroll
        for (int r = 0; r < 8; r++) {
            int row = row0 + rb + r;
            if (row < N_NODES)
                g_xf[(size_t)row * FEATS + col] = acc[r];
        }
    }
}

// ---------------------------------------------------------------------------
// K6: out[d] = relu( sum_{s in nbrs(d)} xf[s] + bias ).
// One warp per node; float4 per lane; 4-way neighbor unroll for MLP.
// No atomics. Every node written exactly once.
// ---------------------------------------------------------------------------
__global__ void gather_bias_relu_kernel(const float* __restrict__ bias,
                                        float* __restrict__ out) {
    int gtid = blockIdx.x * blockDim.x + threadIdx.x;
    int node = gtid >> 5;
    int lane = threadIdx.x & 31;
    if (node >= N_NODES) return;

    int beg = g_off[node];
    int end = g_off[node + 1];

    float4 acc = reinterpret_cast<const float4*>(bias)[lane];
    const float4* xf4 = reinterpret_cast<const float4*>(g_xf);

    int i = beg;
    for (; i + 4 <= end; i += 4) {
        int s0 = g_bucket[i + 0];
        int s1 = g_bucket[i + 1];
        int s2 = g_bucket[i + 2];
        int s3 = g_bucket[i + 3];
        float4 v0 = xf4[(size_t)s0 * 32 + lane];
        float4 v1 = xf4[(size_t)s1 * 32 + lane];
        float4 v2 = xf4[(size_t)s2 * 32 + lane];
        float4 v3 = xf4[(size_t)s3 * 32 + lane];
        acc.x += (v0.x + v1.x) + (v2.x + v3.x);
        acc.y += (v0.y + v1.y) + (v2.y + v3.y);
        acc.z += (v0.z + v1.z) + (v2.z + v3.z);
        acc.w += (v0.w + v1.w) + (v2.w + v3.w);
    }
    for (; i < end; i++) {
        int s = g_bucket[i];
        float4 v = xf4[(size_t)s * 32 + lane];
        acc.x += v.x; acc.y += v.y; acc.z += v.z; acc.w += v.w;
    }

    float4 r;
    r.x = fmaxf(acc.x, 0.f);
    r.y = fmaxf(acc.y, 0.f);
    r.z = fmaxf(acc.z, 0.f);
    r.w = fmaxf(acc.w, 0.f);
    reinterpret_cast<float4*>(out)[(size_t)node * 32 + lane] = r;
}

// ---------------------------------------------------------------------------
extern "C" void kernel_launch(void* const* d_in, const int* in_sizes, int n_in,
                              void* d_out, int out_size) {
    const float* feat = (const float*)d_in[0];   // [50000,128] f32
    const int*   src  = (const int*)d_in[1];     // [800000] i32
    const int*   dst  = (const int*)d_in[2];     // [800000] i32
    const float* W    = (const float*)d_in[3];   // [128,128] f32
    const float* bias = (const float*)d_in[4];   // [128] f32
    float*       out  = (float*)d_out;           // [50000,128] f32

    (void)in_sizes; (void)n_in; (void)out_size;

    const int smem_bytes = (FEATS * WT_STRIDE + TILE_R * FEATS) * sizeof(float); // ~82.4 KB
    cudaFuncSetAttribute(gemm_kernel,
                         cudaFuncAttributeMaxDynamicSharedMemorySize, smem_bytes);

    // CSR build
    zero_cnt_kernel<<<(N_NODES + 256) / 256, 256>>>();
    hist_kernel<<<(N_EDGES + 255) / 256, 256>>>(dst);
    scan_kernel<<<1, 1024>>>();
    fill_kernel<<<(N_EDGES + 255) / 256, 256>>>(src, dst);

    // Transform: xf = feat @ W^T
    gemm_kernel<<<(N_NODES + TILE_R - 1) / TILE_R, FEATS, smem_bytes>>>(feat, W);

    // Gather + bias + relu
    {
        long long threads = (long long)N_NODES * 32;
        int blocks = (int)((threads + 255) / 256);
        gather_bias_relu_kernel<<<blocks, 256>>>(bias, out);
    }
}

// round 5
// speedup vs baseline: 1.9820x; 1.4454x over previous
#include <cuda_runtime.h>
#include <cuda_bf16.h>

#define N_NODES 50000
#define N_EDGES 800000
#define FEATS   128
#define TILE_R  32
#define WC_STRIDE 132   // 132*4=528 B: rows 16B-aligned for per-lane LDS.128
#define SCAN_BLK 1024
#define SCAN_GRID ((N_NODES + SCAN_BLK - 1) / SCAN_BLK)   // 49

// ---------------- device scratch (alloc-free rule: __device__ globals) -----
__device__ float g_xf[(size_t)N_NODES * FEATS];   // feat @ W^T
__device__ int   g_cnt[N_NODES];                  // per-dst degree
__device__ int   g_off[N_NODES + 1];              // CSR offsets
__device__ int   g_cur[N_NODES];                  // fill cursors
__device__ int   g_bucket[N_EDGES];               // src ids bucketed by dst
__device__ int   g_part[SCAN_GRID];               // per-block scan partials

// ---------------------------------------------------------------------------
// K1: zero degree counters (every replay — graph determinism).
// ---------------------------------------------------------------------------
__global__ void zero_cnt_kernel() {
    int i = blockIdx.x * blockDim.x + threadIdx.x;
    if (i < N_NODES) g_cnt[i] = 0;
}

// ---------------------------------------------------------------------------
// K2: histogram of dst.
// ---------------------------------------------------------------------------
__global__ void hist_kernel(const int* __restrict__ dst) {
    int e = blockIdx.x * blockDim.x + threadIdx.x;
    if (e < N_EDGES) {
        int d = dst[e];
        if ((unsigned)d < N_NODES) atomicAdd(&g_cnt[d], 1);
    }
}

// ---------------------------------------------------------------------------
// K3a: per-block exclusive scan of g_cnt -> g_off (block-local), totals -> g_part.
// ---------------------------------------------------------------------------
__global__ void scan_local_kernel() {
    __shared__ int wsum[32];
    int tid  = threadIdx.x;
    int lane = tid & 31;
    int wid  = tid >> 5;
    int idx  = blockIdx.x * SCAN_BLK + tid;

    int x = (idx < N_NODES) ? g_cnt[idx] : 0;

    int v = x;
    #pragma unroll
    for (int d = 1; d < 32; d <<= 1) {
        int t = __shfl_up_sync(0xffffffff, v, d);
        if (lane >= d) v += t;
    }
    if (lane == 31) wsum[wid] = v;
    __syncthreads();
    if (wid == 0) {
        int w = wsum[lane];
        #pragma unroll
        for (int d = 1; d < 32; d <<= 1) {
            int t = __shfl_up_sync(0xffffffff, w, d);
            if (lane >= d) w += t;
        }
        wsum[lane] = w;
    }
    __syncthreads();

    int excl = v - x + ((wid > 0) ? wsum[wid - 1] : 0);
    if (idx < N_NODES) g_off[idx] = excl;
    if (tid == SCAN_BLK - 1) g_part[blockIdx.x] = excl + x;  // block total
}

// ---------------------------------------------------------------------------
// K3b: single small block scans the 49 block totals (exclusive, in place).
// ---------------------------------------------------------------------------
__global__ void scan_part_kernel() {
    __shared__ int s[64];
    int tid = threadIdx.x;  // blockDim = 64
    int x = (tid < SCAN_GRID) ? g_part[tid] : 0;
    s[tid] = x;
    __syncthreads();
    #pragma unroll
    for (int d = 1; d < 64; d <<= 1) {
        int t = (tid >= d) ? s[tid - d] : 0;
        __syncthreads();
        s[tid] += t;
        __syncthreads();
    }
    if (tid < SCAN_GRID) g_part[tid] = s[tid] - x;  // exclusive
}

// ---------------------------------------------------------------------------
// K3c: add block offsets; copy to cursors; finalize sentinel.
// ---------------------------------------------------------------------------
__global__ void scan_add_kernel() {
    int idx = blockIdx.x * blockDim.x + threadIdx.x;
    if (idx < N_NODES) {
        int o = g_off[idx] + g_part[blockIdx.x * blockDim.x / SCAN_BLK + 0];
        // NOTE: blockDim == SCAN_BLK so block b maps to g_part[b]
        o = g_off[idx] + g_part[blockIdx.x];
        g_off[idx] = o;
        g_cur[idx] = o;
    }
    if (idx == 0) g_off[N_NODES] = N_EDGES;
}

// ---------------------------------------------------------------------------
// K4: bucket fill — src ids grouped by dst.
// ---------------------------------------------------------------------------
__global__ void fill_kernel(const int* __restrict__ src,
                            const int* __restrict__ dst) {
    int e = blockIdx.x * blockDim.x + threadIdx.x;
    if (e < N_EDGES) {
        int d = dst[e];
        int s = src[e];
        if ((unsigned)d < N_NODES && (unsigned)s < N_NODES) {
            int pos = atomicAdd(&g_cur[d], 1);
            g_bucket[pos] = s;
        }
    }
}

// ---------------------------------------------------------------------------
// K5: xf = feat @ W^T using packed fma.rn.f32x2 (FFMA2): 2x fp32 per fma slot.
// Block = 128 threads (one per out col), TILE_R=32 rows.
// W consumed row-major -> straight smem copy, stride 132 (rows 16B-aligned).
// acc held as f32x2 pairs over (even-k, odd-k); final result = lo + hi.
// ---------------------------------------------------------------------------
__global__ void gemm_kernel(const float* __restrict__ A,  // [N,128] feat
                            const float* __restrict__ W)  // [128,128] row-major [col][k]
{
    extern __shared__ float sm[];
    float* Wc = sm;                           // [128][132]
    float* As = sm + FEATS * WC_STRIDE;       // [TILE_R][128]

    const int col  = threadIdx.x;
    const int row0 = blockIdx.x * TILE_R;

    // Straight copy of W (no transpose needed for the f32x2 scheme).
    #pragma unroll
    for (int c = 0; c < FEATS; c += 1) {
        // each iteration: 128 lanes copy one row's 128 floats
        Wc[c * WC_STRIDE + col] = W[c * FEATS + col];
    }
    for (int r = 0; r < TILE_R; r++) {
        int row = row0 + r;
        As[r * FEATS + col] = (row < N_NODES) ? A[(size_t)row * FEATS + col] : 0.f;
    }
    __syncthreads();

    const float* wrow = &Wc[col * WC_STRIDE];

    for (int rb = 0; rb < TILE_R; rb += 8) {
        unsigned long long acc[8];
        #pragma unroll
        for (int r = 0; r < 8; r++) acc[r] = 0ull;

        #pragma unroll 8
        for (int k = 0; k < FEATS; k += 4) {
            ulonglong2 wp = *reinterpret_cast<const ulonglong2*>(&wrow[k]);
            #pragma unroll
            for (int r = 0; r < 8; r++) {
                ulonglong2 ap = *reinterpret_cast<const ulonglong2*>(&As[(rb + r) * FEATS + k]);
                asm("fma.rn.f32x2 %0, %1, %2, %0;" : "+l"(acc[r]) : "l"(ap.x), "l"(wp.x));
                asm("fma.rn.f32x2 %0, %1, %2, %0;" : "+l"(acc[r]) : "l"(ap.y), "l"(wp.y));
            }
        }

        #pragma unroll
        for (int r = 0; r < 8; r++) {
            int row = row0 + rb + r;
            if (row < N_NODES) {
                float2 f = *reinterpret_cast<float2*>(&acc[r]);
                g_xf[(size_t)row * FEATS + col] = f.x + f.y;
            }
        }
    }
}

// ---------------------------------------------------------------------------
// K6: out[d] = relu( sum_{s in nbrs(d)} xf[s] + bias ). Warp per node.
// ---------------------------------------------------------------------------
__global__ void gather_bias_relu_kernel(const float* __restrict__ bias,
                                        float* __restrict__ out) {
    int gtid = blockIdx.x * blockDim.x + threadIdx.x;
    int node = gtid >> 5;
    int lane = threadIdx.x & 31;
    if (node >= N_NODES) return;

    int beg = g_off[node];
    int end = g_off[node + 1];

    float4 acc = reinterpret_cast<const float4*>(bias)[lane];
    const float4* xf4 = reinterpret_cast<const float4*>(g_xf);

    int i = beg;
    for (; i + 4 <= end; i += 4) {
        int s0 = g_bucket[i + 0];
        int s1 = g_bucket[i + 1];
        int s2 = g_bucket[i + 2];
        int s3 = g_bucket[i + 3];
        float4 v0 = xf4[(size_t)s0 * 32 + lane];
        float4 v1 = xf4[(size_t)s1 * 32 + lane];
        float4 v2 = xf4[(size_t)s2 * 32 + lane];
        float4 v3 = xf4[(size_t)s3 * 32 + lane];
        acc.x += (v0.x + v1.x) + (v2.x + v3.x);
        acc.y += (v0.y + v1.y) + (v2.y + v3.y);
        acc.z += (v0.z + v1.z) + (v2.z + v3.z);
        acc.w += (v0.w + v1.w) + (v2.w + v3.w);
    }
    for (; i < end; i++) {
        int s = g_bucket[i];
        float4 v = xf4[(size_t)s * 32 + lane];
        acc.x += v.x; acc.y += v.y; acc.z += v.z; acc.w += v.w;
    }

    float4 r;
    r.x = fmaxf(acc.x, 0.f);
    r.y = fmaxf(acc.y, 0.f);
    r.z = fmaxf(acc.z, 0.f);
    r.w = fmaxf(acc.w, 0.f);
    reinterpret_cast<float4*>(out)[(size_t)node * 32 + lane] = r;
}

// ---------------------------------------------------------------------------
extern "C" void kernel_launch(void* const* d_in, const int* in_sizes, int n_in,
                              void* d_out, int out_size) {
    const float* feat = (const float*)d_in[0];   // [50000,128] f32
    const int*   src  = (const int*)d_in[1];     // [800000] i32
    const int*   dst  = (const int*)d_in[2];     // [800000] i32
    const float* W    = (const float*)d_in[3];   // [128,128] f32
    const float* bias = (const float*)d_in[4];   // [128] f32
    float*       out  = (float*)d_out;           // [50000,128] f32

    (void)in_sizes; (void)n_in; (void)out_size;

    const int smem_bytes = (FEATS * WC_STRIDE + TILE_R * FEATS) * sizeof(float); // ~84 KB
    cudaFuncSetAttribute(gemm_kernel,
                         cudaFuncAttributeMaxDynamicSharedMemorySize, smem_bytes);

    // CSR build
    zero_cnt_kernel<<<(N_NODES + 255) / 256, 256>>>();
    hist_kernel<<<(N_EDGES + 255) / 256, 256>>>(dst);
    scan_local_kernel<<<SCAN_GRID, SCAN_BLK>>>();
    scan_part_kernel<<<1, 64>>>();
    scan_add_kernel<<<SCAN_GRID, SCAN_BLK>>>();
    fill_kernel<<<(N_EDGES + 255) / 256, 256>>>(src, dst);

    // Transform: xf = feat @ W^T
    gemm_kernel<<<(N_NODES + TILE_R - 1) / TILE_R, FEATS, smem_bytes>>>(feat, W);

    // Gather + bias + relu
    {
        long long threads = (long long)N_NODES * 32;
        int blocks = (int)((threads + 255) / 256);
        gather_bias_relu_kernel<<<blocks, 256>>>(bias, out);
    }
}

// round 6
// speedup vs baseline: 2.0990x; 1.0591x over previous
#include <cuda_runtime.h>
#include <cuda_bf16.h>

#define N_NODES 50000
#define N_EDGES 800000
#define FEATS   128
#define TILE_R  64
#define WC_STRIDE 132   // 528 B rows: 16B-aligned, conflict-free LDS.128
#define SCAN_BLK 1024
#define SCAN_GRID ((N_NODES + SCAN_BLK - 1) / SCAN_BLK)   // 49

#define GEMM_BLOCKS ((N_NODES + TILE_R - 1) / TILE_R)     // 782
#define EDGE_BLK_EDGES 1024                               // 256 thr * 4 edges
#define EDGE_BLOCKS ((N_EDGES + EDGE_BLK_EDGES - 1) / EDGE_BLK_EDGES) // 782

// ---------------- device scratch (alloc-free rule: __device__ globals) -----
__device__ float g_xf[(size_t)N_NODES * FEATS];   // feat @ W^T
__device__ int   g_cnt[N_NODES];                  // per-dst degree (zeroed by gather for next replay)
__device__ int   g_off[N_NODES + 1];              // CSR offsets
__device__ int   g_cur[N_NODES];                  // fill cursors
__device__ int   g_bucket[N_EDGES];               // src ids bucketed by dst
__device__ int   g_part[SCAN_GRID];               // per-block totals

// ---------------------------------------------------------------------------
// K1: histogram of dst. 4 edges/thread via int4 (independent atomics -> MLP).
// Requires g_cnt == 0 on entry (statics zero-init; gather re-zeroes each call).
// ---------------------------------------------------------------------------
__global__ void hist_kernel(const int* __restrict__ dst) {
    int e0 = blockIdx.x * EDGE_BLK_EDGES + threadIdx.x * 4;
    if (e0 + 3 < N_EDGES) {
        int4 d4 = *reinterpret_cast<const int4*>(dst + e0);
        if ((unsigned)d4.x < N_NODES) atomicAdd(&g_cnt[d4.x], 1);
        if ((unsigned)d4.y < N_NODES) atomicAdd(&g_cnt[d4.y], 1);
        if ((unsigned)d4.z < N_NODES) atomicAdd(&g_cnt[d4.z], 1);
        if ((unsigned)d4.w < N_NODES) atomicAdd(&g_cnt[d4.w], 1);
    } else {
        for (int e = e0; e < N_EDGES; e++) {
            int d = dst[e];
            if ((unsigned)d < N_NODES) atomicAdd(&g_cnt[d], 1);
        }
    }
}

// ---------------------------------------------------------------------------
// K2: per-block exclusive scan of g_cnt -> g_off (block-local); totals -> g_part.
// ---------------------------------------------------------------------------
__global__ void scan_local_kernel() {
    __shared__ int wsum[32];
    int tid  = threadIdx.x;
    int lane = tid & 31;
    int wid  = tid >> 5;
    int idx  = blockIdx.x * SCAN_BLK + tid;

    int x = (idx < N_NODES) ? g_cnt[idx] : 0;

    int v = x;
    #pragma unroll
    for (int d = 1; d < 32; d <<= 1) {
        int t = __shfl_up_sync(0xffffffff, v, d);
        if (lane >= d) v += t;
    }
    if (lane == 31) wsum[wid] = v;
    __syncthreads();
    if (wid == 0) {
        int w = wsum[lane];
        #pragma unroll
        for (int d = 1; d < 32; d <<= 1) {
            int t = __shfl_up_sync(0xffffffff, w, d);
            if (lane >= d) w += t;
        }
        wsum[lane] = w;
    }
    __syncthreads();

    int excl = v - x + ((wid > 0) ? wsum[wid - 1] : 0);
    if (idx < N_NODES) g_off[idx] = excl;
    if (tid == SCAN_BLK - 1) g_part[blockIdx.x] = excl + x;  // block total
}

// ---------------------------------------------------------------------------
// K3: add block offsets (each block sums the <=48 preceding partials itself);
// copy to cursors; sentinel.
// ---------------------------------------------------------------------------
__global__ void scan_add_kernel() {
    __shared__ int s_off;
    int tid = threadIdx.x;
    if (tid < 32) {
        int v = 0;
        for (int j = tid; j < blockIdx.x; j += 32) v += g_part[j];
        #pragma unroll
        for (int d = 16; d > 0; d >>= 1) v += __shfl_down_sync(0xffffffff, v, d);
        if (tid == 0) s_off = v;
    }
    __syncthreads();

    int idx = blockIdx.x * SCAN_BLK + tid;
    if (idx < N_NODES) {
        int o = g_off[idx] + s_off;
        g_off[idx] = o;
        g_cur[idx] = o;
    }
    if (blockIdx.x == 0 && tid == 0) g_off[N_NODES] = N_EDGES;
}

// ---------------------------------------------------------------------------
// K4: FUSED fill + GEMM. Independent work overlapped in one launch:
//   blocks [0, GEMM_BLOCKS)            : xf = feat @ W^T  (FFMA2, TILE_R=64)
//   blocks [GEMM_BLOCKS, +EDGE_BLOCKS) : bucket fill (src grouped by dst)
// 256 threads. Dynamic smem used only by gemm blocks.
// ---------------------------------------------------------------------------
__global__ void fill_gemm_kernel(const int* __restrict__ src,
                                 const int* __restrict__ dst,
                                 const float* __restrict__ A,   // feat [N,128]
                                 const float* __restrict__ W)   // [128,128] row-major
{
    if (blockIdx.x < GEMM_BLOCKS) {
        // ---------------- GEMM role ----------------
        extern __shared__ float sm[];
        float* Wc = sm;                           // [128][132]
        float* As = sm + FEATS * WC_STRIDE;       // [64][128]

        const int tid  = threadIdx.x;
        const int col  = tid & 127;
        const int half = tid >> 7;                // 0/1: rows [0,32) / [32,64)
        const int row0 = blockIdx.x * TILE_R;

        // Stage W (straight copy, float4), stride 132 keeps rows 16B-aligned.
        {
            const float4* W4 = reinterpret_cast<const float4*>(W);
            for (int i = tid; i < FEATS * FEATS / 4; i += 256) {
                int c  = i >> 5;          // row of W
                int k4 = i & 31;          // float4 within row
                float4 w = W4[i];
                *reinterpret_cast<float4*>(&Wc[c * WC_STRIDE + k4 * 4]) = w;
            }
        }
        // Stage A tile (float4), zero-pad past N_NODES.
        {
            float4* As4 = reinterpret_cast<float4*>(As);
            const float4* A4 = reinterpret_cast<const float4*>(A);
            for (int i = tid; i < TILE_R * FEATS / 4; i += 256) {
                int r  = i >> 5;
                int c4 = i & 31;
                int row = row0 + r;
                As4[i] = (row < N_NODES) ? A4[(size_t)row * 32 + c4]
                                         : make_float4(0.f, 0.f, 0.f, 0.f);
            }
        }
        __syncthreads();

        const float* wrow = &Wc[col * WC_STRIDE];

        for (int g = 0; g < 4; g++) {
            int rb = half * 32 + g * 8;
            unsigned long long acc[8];
            #pragma unroll
            for (int r = 0; r < 8; r++) acc[r] = 0ull;

            #pragma unroll 8
            for (int k = 0; k < FEATS; k += 4) {
                ulonglong2 wp = *reinterpret_cast<const ulonglong2*>(&wrow[k]);
                #pragma unroll
                for (int r = 0; r < 8; r++) {
                    ulonglong2 ap = *reinterpret_cast<const ulonglong2*>(&As[(rb + r) * FEATS + k]);
                    asm("fma.rn.f32x2 %0, %1, %2, %0;" : "+l"(acc[r]) : "l"(ap.x), "l"(wp.x));
                    asm("fma.rn.f32x2 %0, %1, %2, %0;" : "+l"(acc[r]) : "l"(ap.y), "l"(wp.y));
                }
            }

            #pragma unroll
            for (int r = 0; r < 8; r++) {
                int row = row0 + rb + r;
                if (row < N_NODES) {
                    float2 f = *reinterpret_cast<float2*>(&acc[r]);
                    g_xf[(size_t)row * FEATS + col] = f.x + f.y;
                }
            }
        }
    } else {
        // ---------------- fill role ----------------
        int b = blockIdx.x - GEMM_BLOCKS;
        int e0 = b * EDGE_BLK_EDGES + threadIdx.x * 4;
        if (e0 + 3 < N_EDGES) {
            int4 s4 = *reinterpret_cast<const int4*>(src + e0);
            int4 d4 = *reinterpret_cast<const int4*>(dst + e0);
            int p0 = ((unsigned)d4.x < N_NODES) ? atomicAdd(&g_cur[d4.x], 1) : -1;
            int p1 = ((unsigned)d4.y < N_NODES) ? atomicAdd(&g_cur[d4.y], 1) : -1;
            int p2 = ((unsigned)d4.z < N_NODES) ? atomicAdd(&g_cur[d4.z], 1) : -1;
            int p3 = ((unsigned)d4.w < N_NODES) ? atomicAdd(&g_cur[d4.w], 1) : -1;
            if (p0 >= 0 && (unsigned)s4.x < N_NODES) g_bucket[p0] = s4.x;
            if (p1 >= 0 && (unsigned)s4.y < N_NODES) g_bucket[p1] = s4.y;
            if (p2 >= 0 && (unsigned)s4.z < N_NODES) g_bucket[p2] = s4.z;
            if (p3 >= 0 && (unsigned)s4.w < N_NODES) g_bucket[p3] = s4.w;
        } else {
            for (int e = e0; e < N_EDGES; e++) {
                int d = dst[e];
                int s = src[e];
                if ((unsigned)d < N_NODES && (unsigned)s < N_NODES) {
                    int pos = atomicAdd(&g_cur[d], 1);
                    g_bucket[pos] = s;
                }
            }
        }
    }
}

// ---------------------------------------------------------------------------
// K5: out[d] = relu( sum_{s in nbrs(d)} xf[s] + bias ). Warp per node.
// Also re-zeroes g_cnt so the NEXT replay's hist starts clean (keeps every
// kernel_launch call's pre/post state identical -> deterministic).
// ---------------------------------------------------------------------------
__global__ void gather_bias_relu_kernel(const float* __restrict__ bias,
                                        float* __restrict__ out) {
    int gtid = blockIdx.x * blockDim.x + threadIdx.x;
    if (gtid < N_NODES) g_cnt[gtid] = 0;   // reset for next replay

    int node = gtid >> 5;
    int lane = threadIdx.x & 31;
    if (node >= N_NODES) return;

    int beg = g_off[node];
    int end = g_off[node + 1];

    float4 acc = reinterpret_cast<const float4*>(bias)[lane];
    const float4* xf4 = reinterpret_cast<const float4*>(g_xf);

    int i = beg;
    for (; i + 4 <= end; i += 4) {
        int s0 = g_bucket[i + 0];
        int s1 = g_bucket[i + 1];
        int s2 = g_bucket[i + 2];
        int s3 = g_bucket[i + 3];
        float4 v0 = xf4[(size_t)s0 * 32 + lane];
        float4 v1 = xf4[(size_t)s1 * 32 + lane];
        float4 v2 = xf4[(size_t)s2 * 32 + lane];
        float4 v3 = xf4[(size_t)s3 * 32 + lane];
        acc.x += (v0.x + v1.x) + (v2.x + v3.x);
        acc.y += (v0.y + v1.y) + (v2.y + v3.y);
        acc.z += (v0.z + v1.z) + (v2.z + v3.z);
        acc.w += (v0.w + v1.w) + (v2.w + v3.w);
    }
    for (; i < end; i++) {
        int s = g_bucket[i];
        float4 v = xf4[(size_t)s * 32 + lane];
        acc.x += v.x; acc.y += v.y; acc.z += v.z; acc.w += v.w;
    }

    float4 r;
    r.x = fmaxf(acc.x, 0.f);
    r.y = fmaxf(acc.y, 0.f);
    r.z = fmaxf(acc.z, 0.f);
    r.w = fmaxf(acc.w, 0.f);
    reinterpret_cast<float4*>(out)[(size_t)node * 32 + lane] = r;
}

// ---------------------------------------------------------------------------
extern "C" void kernel_launch(void* const* d_in, const int* in_sizes, int n_in,
                              void* d_out, int out_size) {
    const float* feat = (const float*)d_in[0];   // [50000,128] f32
    const int*   src  = (const int*)d_in[1];     // [800000] i32
    const int*   dst  = (const int*)d_in[2];     // [800000] i32
    const float* W    = (const float*)d_in[3];   // [128,128] f32
    const float* bias = (const float*)d_in[4];   // [128] f32
    float*       out  = (float*)d_out;           // [50000,128] f32

    (void)in_sizes; (void)n_in; (void)out_size;

    const int smem_bytes = (FEATS * WC_STRIDE + TILE_R * FEATS) * sizeof(float); // ~100 KB
    cudaFuncSetAttribute(fill_gemm_kernel,
                         cudaFuncAttributeMaxDynamicSharedMemorySize, smem_bytes);

    hist_kernel<<<EDGE_BLOCKS, 256>>>(dst);
    scan_local_kernel<<<SCAN_GRID, SCAN_BLK>>>();
    scan_add_kernel<<<SCAN_GRID, SCAN_BLK>>>();
    fill_gemm_kernel<<<GEMM_BLOCKS + EDGE_BLOCKS, 256, smem_bytes>>>(src, dst, feat, W);

    {
        long long threads = (long long)N_NODES * 32;
        int blocks = (int)((threads + 255) / 256);
        gather_bias_relu_kernel<<<blocks, 256>>>(bias, out);
    }
}

// round 7
// speedup vs baseline: 2.3022x; 1.0968x over previous
#include <cuda_runtime.h>
#include <cuda_bf16.h>

#define N_NODES 50000
#define N_EDGES 800000
#define FEATS   128
#define TILE_R  64
#define WS_STRIDE 129   // odd stride: scalar W reads conflict-free (bank = (c+k)%32)
#define SCAN_BLK 1024
#define SCAN_GRID ((N_NODES + SCAN_BLK - 1) / SCAN_BLK)   // 49

#define GEMM_BLOCKS ((N_NODES + TILE_R - 1) / TILE_R)     // 782
#define EDGE_BLK_EDGES 1024                               // 256 thr * 4 edges
#define EDGE_BLOCKS ((N_EDGES + EDGE_BLK_EDGES - 1) / EDGE_BLK_EDGES) // 782

// ---------------- device scratch (alloc-free rule: __device__ globals) -----
__device__ float g_xf[(size_t)N_NODES * FEATS];   // feat @ W^T
__device__ int   g_cnt[N_NODES];                  // per-dst degree (re-zeroed by gather)
__device__ int   g_off[N_NODES + 1];              // CSR offsets
__device__ int   g_cur[N_NODES];                  // fill cursors
__device__ int   g_bucket[N_EDGES];               // src ids bucketed by dst
__device__ int   g_part[SCAN_GRID];               // per-block totals

__device__ __forceinline__ unsigned long long pack_f32x2(float lo, float hi) {
    unsigned long long r;
    asm("mov.b64 %0, {%1, %2};" : "=l"(r) : "f"(lo), "f"(hi));
    return r;
}
#define FMA2(acc, a, w) asm("fma.rn.f32x2 %0, %1, %2, %0;" : "+l"(acc) : "l"(a), "l"(w))

// ---------------------------------------------------------------------------
// K1: histogram of dst. 4 edges/thread via int4 (independent atomics -> MLP).
// Requires g_cnt == 0 on entry (statics zero-init; gather re-zeroes each call).
// ---------------------------------------------------------------------------
__global__ void hist_kernel(const int* __restrict__ dst) {
    int e0 = blockIdx.x * EDGE_BLK_EDGES + threadIdx.x * 4;
    if (e0 + 3 < N_EDGES) {
        int4 d4 = *reinterpret_cast<const int4*>(dst + e0);
        if ((unsigned)d4.x < N_NODES) atomicAdd(&g_cnt[d4.x], 1);
        if ((unsigned)d4.y < N_NODES) atomicAdd(&g_cnt[d4.y], 1);
        if ((unsigned)d4.z < N_NODES) atomicAdd(&g_cnt[d4.z], 1);
        if ((unsigned)d4.w < N_NODES) atomicAdd(&g_cnt[d4.w], 1);
    } else {
        for (int e = e0; e < N_EDGES; e++) {
            int d = dst[e];
            if ((unsigned)d < N_NODES) atomicAdd(&g_cnt[d], 1);
        }
    }
}

// ---------------------------------------------------------------------------
// K2: per-block exclusive scan of g_cnt -> g_off; totals -> g_part.
// ---------------------------------------------------------------------------
__global__ void scan_local_kernel() {
    __shared__ int wsum[32];
    int tid  = threadIdx.x;
    int lane = tid & 31;
    int wid  = tid >> 5;
    int idx  = blockIdx.x * SCAN_BLK + tid;

    int x = (idx < N_NODES) ? g_cnt[idx] : 0;

    int v = x;
    #pragma unroll
    for (int d = 1; d < 32; d <<= 1) {
        int t = __shfl_up_sync(0xffffffff, v, d);
        if (lane >= d) v += t;
    }
    if (lane == 31) wsum[wid] = v;
    __syncthreads();
    if (wid == 0) {
        int w = wsum[lane];
        #pragma unroll
        for (int d = 1; d < 32; d <<= 1) {
            int t = __shfl_up_sync(0xffffffff, w, d);
            if (lane >= d) w += t;
        }
        wsum[lane] = w;
    }
    __syncthreads();

    int excl = v - x + ((wid > 0) ? wsum[wid - 1] : 0);
    if (idx < N_NODES) g_off[idx] = excl;
    if (tid == SCAN_BLK - 1) g_part[blockIdx.x] = excl + x;
}

// ---------------------------------------------------------------------------
// K3: add block offsets (each block sums its <=48 preceding partials);
// copy to cursors; sentinel.
// ---------------------------------------------------------------------------
__global__ void scan_add_kernel() {
    __shared__ int s_off;
    int tid = threadIdx.x;
    if (tid < 32) {
        int v = 0;
        for (int j = tid; j < blockIdx.x; j += 32) v += g_part[j];
        #pragma unroll
        for (int d = 16; d > 0; d >>= 1) v += __shfl_down_sync(0xffffffff, v, d);
        if (tid == 0) s_off = v;
    }
    __syncthreads();

    int idx = blockIdx.x * SCAN_BLK + tid;
    if (idx < N_NODES) {
        int o = g_off[idx] + s_off;
        g_off[idx] = o;
        g_cur[idx] = o;
    }
    if (blockIdx.x == 0 && tid == 0) g_off[N_NODES] = N_EDGES;
}

// ---------------------------------------------------------------------------
// K4: FUSED fill + GEMM (independent work, one launch).
//   blocks [0, GEMM_BLOCKS)            : xf = feat @ W^T
//   blocks [GEMM_BLOCKS, +EDGE_BLOCKS) : bucket fill
// GEMM: 256 thr; warp = 8-row group; thread = 8 rows x 4 cols {lane+32j}.
// W in smem, odd stride 129 -> scalar reads conflict-free.
// A read from GMEM as broadcast ulonglong2 (each element once per block).
// ---------------------------------------------------------------------------
__global__ void __launch_bounds__(256, 2)
fill_gemm_kernel(const int* __restrict__ src,
                 const int* __restrict__ dst,
                 const float* __restrict__ A,   // feat [N,128]
                 const float* __restrict__ W)   // [128,128] row-major
{
    if (blockIdx.x < GEMM_BLOCKS) {
        // ---------------- GEMM role ----------------
        extern __shared__ float Wc[];             // [128][129]

        const int tid  = threadIdx.x;
        const int lane = tid & 31;
        const int wid  = tid >> 5;                // 0..7: 8-row group
        const int row0 = blockIdx.x * TILE_R + wid * 8;

        // Stage W: scalar copy, coalesced LDG, conflict-free STS.
        for (int i = tid; i < FEATS * FEATS; i += 256) {
            int c = i >> 7, k = i & 127;
            Wc[c * WS_STRIDE + k] = W[i];
        }
        __syncthreads();

        // Clamped per-row A offsets (in ulonglong2 units); stores are guarded.
        const ulonglong2* A2 = reinterpret_cast<const ulonglong2*>(A);
        int abase[8];
        #pragma unroll
        for (int r = 0; r < 8; r++) {
            int row = row0 + r;
            abase[r] = (row < N_NODES ? row : N_NODES - 1) * 32;
        }

        unsigned long long acc[4][8];
        #pragma unroll
        for (int j = 0; j < 4; j++)
            #pragma unroll
            for (int r = 0; r < 8; r++) acc[j][r] = 0ull;

        #pragma unroll 2
        for (int k = 0; k < FEATS; k += 4) {
            unsigned long long w01[4], w23[4];
            #pragma unroll
            for (int j = 0; j < 4; j++) {
                const float* wr = &Wc[(lane + 32 * j) * WS_STRIDE + k];
                w01[j] = pack_f32x2(wr[0], wr[1]);
                w23[j] = pack_f32x2(wr[2], wr[3]);
            }
            #pragma unroll
            for (int r = 0; r < 8; r++) {
                ulonglong2 a = A2[abase[r] + (k >> 2)];  // broadcast across warp
                #pragma unroll
                for (int j = 0; j < 4; j++) {
                    FMA2(acc[j][r], a.x, w01[j]);
                    FMA2(acc[j][r], a.y, w23[j]);
                }
            }
        }

        #pragma unroll
        for (int r = 0; r < 8; r++) {
            int row = row0 + r;
            if (row < N_NODES) {
                #pragma unroll
                for (int j = 0; j < 4; j++) {
                    float2 f = *reinterpret_cast<float2*>(&acc[j][r]);
                    g_xf[(size_t)row * FEATS + lane + 32 * j] = f.x + f.y;
                }
            }
        }
    } else {
        // ---------------- fill role ----------------
        int b = blockIdx.x - GEMM_BLOCKS;
        int e0 = b * EDGE_BLK_EDGES + threadIdx.x * 4;
        if (e0 + 3 < N_EDGES) {
            int4 s4 = *reinterpret_cast<const int4*>(src + e0);
            int4 d4 = *reinterpret_cast<const int4*>(dst + e0);
            int p0 = ((unsigned)d4.x < N_NODES) ? atomicAdd(&g_cur[d4.x], 1) : -1;
            int p1 = ((unsigned)d4.y < N_NODES) ? atomicAdd(&g_cur[d4.y], 1) : -1;
            int p2 = ((unsigned)d4.z < N_NODES) ? atomicAdd(&g_cur[d4.z], 1) : -1;
            int p3 = ((unsigned)d4.w < N_NODES) ? atomicAdd(&g_cur[d4.w], 1) : -1;
            if (p0 >= 0 && (unsigned)s4.x < N_NODES) g_bucket[p0] = s4.x;
            if (p1 >= 0 && (unsigned)s4.y < N_NODES) g_bucket[p1] = s4.y;
            if (p2 >= 0 && (unsigned)s4.z < N_NODES) g_bucket[p2] = s4.z;
            if (p3 >= 0 && (unsigned)s4.w < N_NODES) g_bucket[p3] = s4.w;
        } else {
            for (int e = e0; e < N_EDGES; e++) {
                int d = dst[e];
                int s = src[e];
                if ((unsigned)d < N_NODES && (unsigned)s < N_NODES) {
                    int pos = atomicAdd(&g_cur[d], 1);
                    g_bucket[pos] = s;
                }
            }
        }
    }
}

// ---------------------------------------------------------------------------
// K5: out[d] = relu( sum_{s in nbrs(d)} xf[s] + bias ). Warp per node.
// Also re-zeroes g_cnt for the next replay (state identical at call bounds).
// ---------------------------------------------------------------------------
__global__ void gather_bias_relu_kernel(const float* __restrict__ bias,
                                        float* __restrict__ out) {
    int gtid = blockIdx.x * blockDim.x + threadIdx.x;
    if (gtid < N_NODES) g_cnt[gtid] = 0;

    int node = gtid >> 5;
    int lane = threadIdx.x & 31;
    if (node >= N_NODES) return;

    int beg = g_off[node];
    int end = g_off[node + 1];

    float4 acc = reinterpret_cast<const float4*>(bias)[lane];
    const float4* xf4 = reinterpret_cast<const float4*>(g_xf);

    int i = beg;
    for (; i + 4 <= end; i += 4) {
        int s0 = g_bucket[i + 0];
        int s1 = g_bucket[i + 1];
        int s2 = g_bucket[i + 2];
        int s3 = g_bucket[i + 3];
        float4 v0 = xf4[(size_t)s0 * 32 + lane];
        float4 v1 = xf4[(size_t)s1 * 32 + lane];
        float4 v2 = xf4[(size_t)s2 * 32 + lane];
        float4 v3 = xf4[(size_t)s3 * 32 + lane];
        acc.x += (v0.x + v1.x) + (v2.x + v3.x);
        acc.y += (v0.y + v1.y) + (v2.y + v3.y);
        acc.z += (v0.z + v1.z) + (v2.z + v3.z);
        acc.w += (v0.w + v1.w) + (v2.w + v3.w);
    }
    for (; i < end; i++) {
        int s = g_bucket[i];
        float4 v = xf4[(size_t)s * 32 + lane];
        acc.x += v.x; acc.y += v.y; acc.z += v.z; acc.w += v.w;
    }

    float4 r;
    r.x = fmaxf(acc.x, 0.f);
    r.y = fmaxf(acc.y, 0.f);
    r.z = fmaxf(acc.z, 0.f);
    r.w = fmaxf(acc.w, 0.f);
    reinterpret_cast<float4*>(out)[(size_t)node * 32 + lane] = r;
}

// ---------------------------------------------------------------------------
extern "C" void kernel_launch(void* const* d_in, const int* in_sizes, int n_in,
                              void* d_out, int out_size) {
    const float* feat = (const float*)d_in[0];   // [50000,128] f32
    const int*   src  = (const int*)d_in[1];     // [800000] i32
    const int*   dst  = (const int*)d_in[2];     // [800000] i32
    const float* W    = (const float*)d_in[3];   // [128,128] f32
    const float* bias = (const float*)d_in[4];   // [128] f32
    float*       out  = (float*)d_out;           // [50000,128] f32

    (void)in_sizes; (void)n_in; (void)out_size;

    const int smem_bytes = FEATS * WS_STRIDE * sizeof(float);  // 66,048 B
    cudaFuncSetAttribute(fill_gemm_kernel,
                         cudaFuncAttributeMaxDynamicSharedMemorySize, smem_bytes);

    hist_kernel<<<EDGE_BLOCKS, 256>>>(dst);
    scan_local_kernel<<<SCAN_GRID, SCAN_BLK>>>();
    scan_add_kernel<<<SCAN_GRID, SCAN_BLK>>>();
    fill_gemm_kernel<<<GEMM_BLOCKS + EDGE_BLOCKS, 256, smem_bytes>>>(src, dst, feat, W);

    {
        long long threads = (long long)N_NODES * 32;
        int blocks = (int)((threads + 255) / 256);
        gather_bias_relu_kernel<<<blocks, 256>>>(bias, out);
    }
}

// round 8
// speedup vs baseline: 2.9120x; 1.2649x over previous
#include <cuda_runtime.h>
#include <cuda_bf16.h>

#define N_NODES 50000
#define N_EDGES 800000
#define FEATS   128
#define TILE_R  64
#define WS_STRIDE 129   // odd stride: scalar W reads conflict-free (bank=(c+k)%32)
#define SCAN_BLK 1024
#define SCAN_GRID ((N_NODES + SCAN_BLK - 1) / SCAN_BLK)   // 49

#define GEMM_BLOCKS ((N_NODES + TILE_R - 1) / TILE_R)     // 782
#define EDGE_BLK_EDGES 1024                               // 256 thr * 4 edges
#define EDGE_BLOCKS ((N_EDGES + EDGE_BLK_EDGES - 1) / EDGE_BLK_EDGES) // 782

// ---------------- device scratch (alloc-free rule: __device__ globals) -----
__device__ float g_xf[(size_t)N_NODES * FEATS];   // feat @ W^T
__device__ int   g_cnt[N_NODES];                  // per-dst degree (re-zeroed by gather)
__device__ int   g_off[N_NODES + 1];              // CSR offsets
__device__ int   g_cur[N_NODES];                  // fill cursors
__device__ int   g_bucket[N_EDGES];               // src ids bucketed by dst
__device__ int   g_part[SCAN_GRID];               // per-block totals

__device__ __forceinline__ unsigned long long pack_f32x2(float lo, float hi) {
    unsigned long long r;
    asm("mov.b64 %0, {%1, %2};" : "=l"(r) : "f"(lo), "f"(hi));
    return r;
}
#define FMA2(acc, a, w) asm("fma.rn.f32x2 %0, %1, %2, %0;" : "+l"(acc) : "l"(a), "l"(w))

// ---------------------------------------------------------------------------
// K1: histogram of dst. 4 edges/thread via int4.
// Requires g_cnt == 0 on entry (statics zero-init; gather re-zeroes each call).
// ---------------------------------------------------------------------------
__global__ void hist_kernel(const int* __restrict__ dst) {
    int e0 = blockIdx.x * EDGE_BLK_EDGES + threadIdx.x * 4;
    if (e0 + 3 < N_EDGES) {
        int4 d4 = *reinterpret_cast<const int4*>(dst + e0);
        if ((unsigned)d4.x < N_NODES) atomicAdd(&g_cnt[d4.x], 1);
        if ((unsigned)d4.y < N_NODES) atomicAdd(&g_cnt[d4.y], 1);
        if ((unsigned)d4.z < N_NODES) atomicAdd(&g_cnt[d4.z], 1);
        if ((unsigned)d4.w < N_NODES) atomicAdd(&g_cnt[d4.w], 1);
    } else {
        for (int e = e0; e < N_EDGES; e++) {
            int d = dst[e];
            if ((unsigned)d < N_NODES) atomicAdd(&g_cnt[d], 1);
        }
    }
}

// ---------------------------------------------------------------------------
// K2: per-block exclusive scan of g_cnt -> g_off; totals -> g_part.
// ---------------------------------------------------------------------------
__global__ void scan_local_kernel() {
    __shared__ int wsum[32];
    int tid  = threadIdx.x;
    int lane = tid & 31;
    int wid  = tid >> 5;
    int idx  = blockIdx.x * SCAN_BLK + tid;

    int x = (idx < N_NODES) ? g_cnt[idx] : 0;

    int v = x;
    #pragma unroll
    for (int d = 1; d < 32; d <<= 1) {
        int t = __shfl_up_sync(0xffffffff, v, d);
        if (lane >= d) v += t;
    }
    if (lane == 31) wsum[wid] = v;
    __syncthreads();
    if (wid == 0) {
        int w = wsum[lane];
        #pragma unroll
        for (int d = 1; d < 32; d <<= 1) {
            int t = __shfl_up_sync(0xffffffff, w, d);
            if (lane >= d) w += t;
        }
        wsum[lane] = w;
    }
    __syncthreads();

    int excl = v - x + ((wid > 0) ? wsum[wid - 1] : 0);
    if (idx < N_NODES) g_off[idx] = excl;
    if (tid == SCAN_BLK - 1) g_part[blockIdx.x] = excl + x;
}

// ---------------------------------------------------------------------------
// K3: add block offsets; copy to cursors; sentinel.
// ---------------------------------------------------------------------------
__global__ void scan_add_kernel() {
    __shared__ int s_off;
    int tid = threadIdx.x;
    if (tid < 32) {
        int v = 0;
        for (int j = tid; j < blockIdx.x; j += 32) v += g_part[j];
        #pragma unroll
        for (int d = 16; d > 0; d >>= 1) v += __shfl_down_sync(0xffffffff, v, d);
        if (tid == 0) s_off = v;
    }
    __syncthreads();

    int idx = blockIdx.x * SCAN_BLK + tid;
    if (idx < N_NODES) {
        int o = g_off[idx] + s_off;
        g_off[idx] = o;
        g_cur[idx] = o;
    }
    if (blockIdx.x == 0 && tid == 0) g_off[N_NODES] = N_EDGES;
}

// ---------------------------------------------------------------------------
// K4: FUSED fill + GEMM (independent work, one launch).
//   blocks [0, GEMM_BLOCKS)            : xf = feat @ W^T
//   blocks [GEMM_BLOCKS, +EDGE_BLOCKS) : bucket fill
// GEMM: warp = 8-row group; thread = 8 rows x 4 cols {lane+32j}.
//   W in smem stride 129 (scalar reads conflict-free),
//   A tile in smem (broadcast LDS.128, 29-cyc latency).
// ---------------------------------------------------------------------------
__global__ void __launch_bounds__(256, 2)
fill_gemm_kernel(const int* __restrict__ src,
                 const int* __restrict__ dst,
                 const float* __restrict__ A,   // feat [N,128]
                 const float* __restrict__ W)   // [128,128] row-major
{
    if (blockIdx.x < GEMM_BLOCKS) {
        // ---------------- GEMM role ----------------
        extern __shared__ float sm[];
        float* Wc = sm;                         // [128][129] = 66,048 B
        float* As = sm + FEATS * WS_STRIDE;     // [64][128]  = 32,768 B

        const int tid  = threadIdx.x;
        const int lane = tid & 31;
        const int wid  = tid >> 5;              // 0..7: 8-row group
        const int row0 = blockIdx.x * TILE_R + wid * 8;

        // Stage W: coalesced LDG, conflict-free scalar STS.
        for (int i = tid; i < FEATS * FEATS; i += 256) {
            int c = i >> 7, k = i & 127;
            Wc[c * WS_STRIDE + k] = W[i];
        }
        // Stage A tile: coalesced float4, zero-pad past N_NODES.
        {
            const float4* A4 = reinterpret_cast<const float4*>(A);
            float4* As4 = reinterpret_cast<float4*>(As);
            int rbase = blockIdx.x * TILE_R;
            #pragma unroll
            for (int t = 0; t < 8; t++) {
                int i = tid + t * 256;          // 0..2047
                int r  = i >> 5;
                int c4 = i & 31;
                int row = rbase + r;
                As4[i] = (row < N_NODES) ? A4[(size_t)row * 32 + c4]
                                         : make_float4(0.f, 0.f, 0.f, 0.f);
            }
        }
        __syncthreads();

        unsigned long long acc[4][8];
        #pragma unroll
        for (int j = 0; j < 4; j++)
            #pragma unroll
            for (int r = 0; r < 8; r++) acc[j][r] = 0ull;

        #pragma unroll 2
        for (int k = 0; k < FEATS; k += 4) {
            unsigned long long w01[4], w23[4];
            #pragma unroll
            for (int j = 0; j < 4; j++) {
                const float* wr = &Wc[(lane + 32 * j) * WS_STRIDE + k];
                w01[j] = pack_f32x2(wr[0], wr[1]);
                w23[j] = pack_f32x2(wr[2], wr[3]);
            }
            #pragma unroll
            for (int r = 0; r < 8; r++) {
                // broadcast LDS.128 — same address across warp, 1 wavefront
                ulonglong2 a = *reinterpret_cast<const ulonglong2*>(
                    &As[(wid * 8 + r) * FEATS + k]);
                #pragma unroll
                for (int j = 0; j < 4; j++) {
                    FMA2(acc[j][r], a.x, w01[j]);
                    FMA2(acc[j][r], a.y, w23[j]);
                }
            }
        }

        #pragma unroll
        for (int r = 0; r < 8; r++) {
            int row = row0 + r;
            if (row < N_NODES) {
                #pragma unroll
                for (int j = 0; j < 4; j++) {
                    float2 f = *reinterpret_cast<float2*>(&acc[j][r]);
                    g_xf[(size_t)row * FEATS + lane + 32 * j] = f.x + f.y;
                }
            }
        }
    } else {
        // ---------------- fill role ----------------
        int b = blockIdx.x - GEMM_BLOCKS;
        int e0 = b * EDGE_BLK_EDGES + threadIdx.x * 4;
        if (e0 + 3 < N_EDGES) {
            int4 s4 = *reinterpret_cast<const int4*>(src + e0);
            int4 d4 = *reinterpret_cast<const int4*>(dst + e0);
            int p0 = ((unsigned)d4.x < N_NODES) ? atomicAdd(&g_cur[d4.x], 1) : -1;
            int p1 = ((unsigned)d4.y < N_NODES) ? atomicAdd(&g_cur[d4.y], 1) : -1;
            int p2 = ((unsigned)d4.z < N_NODES) ? atomicAdd(&g_cur[d4.z], 1) : -1;
            int p3 = ((unsigned)d4.w < N_NODES) ? atomicAdd(&g_cur[d4.w], 1) : -1;
            if (p0 >= 0 && (unsigned)s4.x < N_NODES) g_bucket[p0] = s4.x;
            if (p1 >= 0 && (unsigned)s4.y < N_NODES) g_bucket[p1] = s4.y;
            if (p2 >= 0 && (unsigned)s4.z < N_NODES) g_bucket[p2] = s4.z;
            if (p3 >= 0 && (unsigned)s4.w < N_NODES) g_bucket[p3] = s4.w;
        } else {
            for (int e = e0; e < N_EDGES; e++) {
                int d = dst[e];
                int s = src[e];
                if ((unsigned)d < N_NODES && (unsigned)s < N_NODES) {
                    int pos = atomicAdd(&g_cur[d], 1);
                    g_bucket[pos] = s;
                }
            }
        }
    }
}

// ---------------------------------------------------------------------------
// K5: out[d] = relu( sum_{s in nbrs(d)} xf[s] + bias ). Warp per node.
// Re-zeroes g_cnt for the next replay (state identical at call boundaries).
// ---------------------------------------------------------------------------
__global__ void gather_bias_relu_kernel(const float* __restrict__ bias,
                                        float* __restrict__ out) {
    int gtid = blockIdx.x * blockDim.x + threadIdx.x;
    if (gtid < N_NODES) g_cnt[gtid] = 0;

    int node = gtid >> 5;
    int lane = threadIdx.x & 31;
    if (node >= N_NODES) return;

    int beg = g_off[node];
    int end = g_off[node + 1];

    float4 acc = reinterpret_cast<const float4*>(bias)[lane];
    const float4* xf4 = reinterpret_cast<const float4*>(g_xf);

    int i = beg;
    for (; i + 4 <= end; i += 4) {
        int s0 = g_bucket[i + 0];
        int s1 = g_bucket[i + 1];
        int s2 = g_bucket[i + 2];
        int s3 = g_bucket[i + 3];
        float4 v0 = xf4[(size_t)s0 * 32 + lane];
        float4 v1 = xf4[(size_t)s1 * 32 + lane];
        float4 v2 = xf4[(size_t)s2 * 32 + lane];
        float4 v3 = xf4[(size_t)s3 * 32 + lane];
        acc.x += (v0.x + v1.x) + (v2.x + v3.x);
        acc.y += (v0.y + v1.y) + (v2.y + v3.y);
        acc.z += (v0.z + v1.z) + (v2.z + v3.z);
        acc.w += (v0.w + v1.w) + (v2.w + v3.w);
    }
    for (; i < end; i++) {
        int s = g_bucket[i];
        float4 v = xf4[(size_t)s * 32 + lane];
        acc.x += v.x; acc.y += v.y; acc.z += v.z; acc.w += v.w;
    }

    float4 r;
    r.x = fmaxf(acc.x, 0.f);
    r.y = fmaxf(acc.y, 0.f);
    r.z = fmaxf(acc.z, 0.f);
    r.w = fmaxf(acc.w, 0.f);
    reinterpret_cast<float4*>(out)[(size_t)node * 32 + lane] = r;
}

// ---------------------------------------------------------------------------
extern "C" void kernel_launch(void* const* d_in, const int* in_sizes, int n_in,
                              void* d_out, int out_size) {
    const float* feat = (const float*)d_in[0];   // [50000,128] f32
    const int*   src  = (const int*)d_in[1];     // [800000] i32
    const int*   dst  = (const int*)d_in[2];     // [800000] i32
    const float* W    = (const float*)d_in[3];   // [128,128] f32
    const float* bias = (const float*)d_in[4];   // [128] f32
    float*       out  = (float*)d_out;           // [50000,128] f32

    (void)in_sizes; (void)n_in; (void)out_size;

    const int smem_bytes = (FEATS * WS_STRIDE + TILE_R * FEATS) * sizeof(float); // 98,816 B
    cudaFuncSetAttribute(fill_gemm_kernel,
                         cudaFuncAttributeMaxDynamicSharedMemorySize, smem_bytes);

    hist_kernel<<<EDGE_BLOCKS, 256>>>(dst);
    scan_local_kernel<<<SCAN_GRID, SCAN_BLK>>>();
    scan_add_kernel<<<SCAN_GRID, SCAN_BLK>>>();
    fill_gemm_kernel<<<GEMM_BLOCKS + EDGE_BLOCKS, 256, smem_bytes>>>(src, dst, feat, W);

    {
        long long threads = (long long)N_NODES * 32;
        int blocks = (int)((threads + 255) / 256);
        gather_bias_relu_kernel<<<blocks, 256>>>(bias, out);
    }
}